// round 1
// baseline (speedup 1.0000x reference)
#include <cuda_runtime.h>
#include <math.h>

#define BN 4
#define SS 4096
#define CC 256
#define M_TOT (BN*SS)   // 16384 rows

// ---------------- scratch (static device allocations are allowed) -------------
__device__ float g_xn[(size_t)BN*SS*CC];
__device__ float g_q [(size_t)BN*SS*CC];
__device__ float g_k [(size_t)BN*SS*CC];
__device__ float g_v [(size_t)BN*SS*CC];
__device__ float g_o [(size_t)BN*SS*CC];

// ---------------- LayerNorm: one block per row of 256 ------------------------
__global__ void ln_kernel(const float* __restrict__ x,
                          const float* __restrict__ gamma,
                          const float* __restrict__ beta,
                          float* __restrict__ out) {
    int row = blockIdx.x;
    int t   = threadIdx.x;
    const float* xr = x + (size_t)row * CC;
    float v = xr[t];

    __shared__ float red[8];
    __shared__ float s_mu, s_rstd;

    float s = v;
    #pragma unroll
    for (int o = 16; o; o >>= 1) s += __shfl_xor_sync(0xffffffffu, s, o);
    if ((t & 31) == 0) red[t >> 5] = s;
    __syncthreads();
    if (t == 0) {
        float m = 0.f;
        #pragma unroll
        for (int i = 0; i < 8; i++) m += red[i];
        s_mu = m * (1.0f / CC);
    }
    __syncthreads();
    float mu = s_mu;
    float d  = v - mu;

    s = d * d;
    #pragma unroll
    for (int o = 16; o; o >>= 1) s += __shfl_xor_sync(0xffffffffu, s, o);
    if ((t & 31) == 0) red[t >> 5] = s;
    __syncthreads();
    if (t == 0) {
        float m = 0.f;
        #pragma unroll
        for (int i = 0; i < 8; i++) m += red[i];
        s_rstd = rsqrtf(m * (1.0f / CC) + 1e-3f);
    }
    __syncthreads();

    out[(size_t)row * CC + t] = d * s_rstd * gamma[t] + beta[t];
}

// ---------------- generic GEMM: out[M,256] = A[M,256] @ W[256,256] + bias (+res)
__global__ __launch_bounds__(256) void gemm_kernel(
        const float* __restrict__ A, const float* __restrict__ W,
        const float* __restrict__ bias, const float* __restrict__ res,
        float* __restrict__ out) {
    __shared__ float As[64 * 16];
    __shared__ float Bs[16 * 64];

    int t  = threadIdx.x;
    int tx = t & 15, ty = t >> 4;
    int m0 = blockIdx.y * 64, n0 = blockIdx.x * 64;

    float acc[4][4];
    #pragma unroll
    for (int i = 0; i < 4; i++)
        #pragma unroll
        for (int j = 0; j < 4; j++) acc[i][j] = 0.f;

    for (int kk = 0; kk < CC; kk += 16) {
        int r  = t >> 2, cq = (t & 3) * 4;
        *(float4*)&As[r * 16 + cq] =
            *(const float4*)&A[(size_t)(m0 + r) * CC + kk + cq];
        int kr = t >> 4, c4 = (t & 15) * 4;
        *(float4*)&Bs[kr * 64 + c4] =
            *(const float4*)&W[(size_t)(kk + kr) * CC + n0 + c4];
        __syncthreads();

        #pragma unroll
        for (int k = 0; k < 16; k++) {
            float a0 = As[(ty * 4 + 0) * 16 + k];
            float a1 = As[(ty * 4 + 1) * 16 + k];
            float a2 = As[(ty * 4 + 2) * 16 + k];
            float a3 = As[(ty * 4 + 3) * 16 + k];
            float4 bv = *(float4*)&Bs[k * 64 + tx * 4];
            acc[0][0] = fmaf(a0, bv.x, acc[0][0]); acc[0][1] = fmaf(a0, bv.y, acc[0][1]);
            acc[0][2] = fmaf(a0, bv.z, acc[0][2]); acc[0][3] = fmaf(a0, bv.w, acc[0][3]);
            acc[1][0] = fmaf(a1, bv.x, acc[1][0]); acc[1][1] = fmaf(a1, bv.y, acc[1][1]);
            acc[1][2] = fmaf(a1, bv.z, acc[1][2]); acc[1][3] = fmaf(a1, bv.w, acc[1][3]);
            acc[2][0] = fmaf(a2, bv.x, acc[2][0]); acc[2][1] = fmaf(a2, bv.y, acc[2][1]);
            acc[2][2] = fmaf(a2, bv.z, acc[2][2]); acc[2][3] = fmaf(a2, bv.w, acc[2][3]);
            acc[3][0] = fmaf(a3, bv.x, acc[3][0]); acc[3][1] = fmaf(a3, bv.y, acc[3][1]);
            acc[3][2] = fmaf(a3, bv.z, acc[3][2]); acc[3][3] = fmaf(a3, bv.w, acc[3][3]);
        }
        __syncthreads();
    }

    int col = n0 + tx * 4;
    float4 bb = *(const float4*)&bias[col];
    #pragma unroll
    for (int i = 0; i < 4; i++) {
        int row = m0 + ty * 4 + i;
        float4 o;
        o.x = acc[i][0] + bb.x; o.y = acc[i][1] + bb.y;
        o.z = acc[i][2] + bb.z; o.w = acc[i][3] + bb.w;
        if (res) {
            float4 rr = *(const float4*)&res[(size_t)row * CC + col];
            o.x += rr.x; o.y += rr.y; o.z += rr.z; o.w += rr.w;
        }
        *(float4*)&out[(size_t)row * CC + col] = o;
    }
}

// ---------------- flash attention: Bq=Bk=64, D=256, online softmax ------------
#define FLASH_SMEM_FLOATS (3 * 64 * 256 + 64 * 68)
#define FLASH_SMEM_BYTES  (FLASH_SMEM_FLOATS * 4)

__global__ __launch_bounds__(256) void flash_kernel(
        const float* __restrict__ q, const float* __restrict__ k,
        const float* __restrict__ v, float* __restrict__ o) {
    extern __shared__ float sm[];
    float* Qs = sm;                       // [64][256]
    float* Ks = sm + 64 * 256;            // [64][256], float4-swizzled
    float* Vs = sm + 2 * 64 * 256;        // [64][256]
    float* Ps = sm + 3 * 64 * 256;        // [64][68]

    int b = blockIdx.y, qb = blockIdx.x;
    const float4* qp = (const float4*)(q + ((size_t)b * SS + qb * 64) * CC);
    const float4* kp = (const float4*)(k + (size_t)b * SS * CC);
    const float4* vp = (const float4*)(v + (size_t)b * SS * CC);

    int t = threadIdx.x, tx = t & 15, ty = t >> 4;

    for (int i = t; i < 4096; i += 256) ((float4*)Qs)[i] = qp[i];

    float m[4], l[4];
    float4 O[4][4];
    #pragma unroll
    for (int i = 0; i < 4; i++) {
        m[i] = -1e30f; l[i] = 0.f;
        #pragma unroll
        for (int j = 0; j < 4; j++) O[i][j] = make_float4(0.f, 0.f, 0.f, 0.f);
    }

    for (int kt = 0; kt < 64; kt++) {
        const float4* ksrc = kp + (size_t)kt * 4096;
        const float4* vsrc = vp + (size_t)kt * 4096;
        for (int i = t; i < 4096; i += 256) {
            int r = i >> 6, c4 = i & 63;
            ((float4*)Ks)[r * 64 + (c4 ^ ((r >> 2) & 15))] = ksrc[i];
            ((float4*)Vs)[i] = vsrc[i];
        }
        __syncthreads();

        // ---- scores: S[4][4] = Q(rows ty*4..) . K(cols tx*4..) over D=256 ----
        float s[4][4];
        #pragma unroll
        for (int i = 0; i < 4; i++)
            #pragma unroll
            for (int j = 0; j < 4; j++) s[i][j] = 0.f;

        #pragma unroll 4
        for (int kk = 0; kk < 64; kk++) {       // float4 units of D
            float4 a[4], kb[4];
            #pragma unroll
            for (int i = 0; i < 4; i++)
                a[i] = ((float4*)Qs)[(ty * 4 + i) * 64 + kk];
            #pragma unroll
            for (int j = 0; j < 4; j++) {
                int r = tx * 4 + j;
                kb[j] = ((float4*)Ks)[r * 64 + (kk ^ ((r >> 2) & 15))];
            }
            #pragma unroll
            for (int i = 0; i < 4; i++)
                #pragma unroll
                for (int j = 0; j < 4; j++) {
                    s[i][j] = fmaf(a[i].x, kb[j].x, s[i][j]);
                    s[i][j] = fmaf(a[i].y, kb[j].y, s[i][j]);
                    s[i][j] = fmaf(a[i].z, kb[j].z, s[i][j]);
                    s[i][j] = fmaf(a[i].w, kb[j].w, s[i][j]);
                }
        }

        // ---- online softmax update ----
        const float scale = 0.0625f;  // 256^-0.5
        #pragma unroll
        for (int i = 0; i < 4; i++) {
            float tm = -1e30f;
            #pragma unroll
            for (int j = 0; j < 4; j++) { s[i][j] *= scale; tm = fmaxf(tm, s[i][j]); }
            #pragma unroll
            for (int off = 8; off; off >>= 1)
                tm = fmaxf(tm, __shfl_xor_sync(0xffffffffu, tm, off));
            float mnew = fmaxf(m[i], tm);
            float corr = __expf(m[i] - mnew);
            float rsum = 0.f;
            #pragma unroll
            for (int j = 0; j < 4; j++) {
                float p = __expf(s[i][j] - mnew);
                s[i][j] = p; rsum += p;
            }
            #pragma unroll
            for (int off = 8; off; off >>= 1)
                rsum += __shfl_xor_sync(0xffffffffu, rsum, off);
            l[i] = l[i] * corr + rsum;
            m[i] = mnew;
            #pragma unroll
            for (int j = 0; j < 4; j++) {
                O[i][j].x *= corr; O[i][j].y *= corr;
                O[i][j].z *= corr; O[i][j].w *= corr;
            }
            *(float4*)&Ps[(ty * 4 + i) * 68 + tx * 4] =
                make_float4(s[i][0], s[i][1], s[i][2], s[i][3]);
        }
        __syncthreads();

        // ---- PV: O[64][256] += P[64][64] @ V[64][256] ----
        #pragma unroll 4
        for (int s4 = 0; s4 < 16; s4++) {
            float4 p4[4];
            #pragma unroll
            for (int i = 0; i < 4; i++)
                p4[i] = *(float4*)&Ps[(ty * 4 + i) * 68 + s4 * 4];
            #pragma unroll
            for (int ss = 0; ss < 4; ss++) {
                float4 vv[4];
                #pragma unroll
                for (int jj = 0; jj < 4; jj++)
                    vv[jj] = ((float4*)Vs)[(s4 * 4 + ss) * 64 + jj * 16 + tx];
                #pragma unroll
                for (int i = 0; i < 4; i++) {
                    float p = (ss == 0) ? p4[i].x : (ss == 1) ? p4[i].y
                            : (ss == 2) ? p4[i].z : p4[i].w;
                    #pragma unroll
                    for (int jj = 0; jj < 4; jj++) {
                        O[i][jj].x = fmaf(p, vv[jj].x, O[i][jj].x);
                        O[i][jj].y = fmaf(p, vv[jj].y, O[i][jj].y);
                        O[i][jj].z = fmaf(p, vv[jj].z, O[i][jj].z);
                        O[i][jj].w = fmaf(p, vv[jj].w, O[i][jj].w);
                    }
                }
            }
        }
        __syncthreads();
    }

    // ---- epilogue: divide by l, write O ----
    #pragma unroll
    for (int i = 0; i < 4; i++) {
        float inv = 1.0f / l[i];
        size_t row = (size_t)b * SS + qb * 64 + ty * 4 + i;
        #pragma unroll
        for (int jj = 0; jj < 4; jj++) {
            float4 val;
            val.x = O[i][jj].x * inv; val.y = O[i][jj].y * inv;
            val.z = O[i][jj].z * inv; val.w = O[i][jj].w * inv;
            *(float4*)&o[row * CC + jj * 64 + tx * 4] = val;
        }
    }
}

// ---------------- launcher ----------------------------------------------------
extern "C" void kernel_launch(void* const* d_in, const int* in_sizes, int n_in,
                              void* d_out, int out_size) {
    const float* inputs  = (const float*)d_in[0];
    const float* context = (const float*)d_in[1];
    const float* Wq = (const float*)d_in[2];
    const float* bq = (const float*)d_in[3];
    const float* Wk = (const float*)d_in[4];
    const float* bk = (const float*)d_in[5];
    const float* Wv = (const float*)d_in[6];
    const float* bv = (const float*)d_in[7];
    const float* Wp = (const float*)d_in[8];
    const float* bp = (const float*)d_in[9];
    const float* gamma = (const float*)d_in[10];
    const float* beta  = (const float*)d_in[11];
    float* out = (float*)d_out;

    float *xn, *q, *k, *v, *o;
    cudaGetSymbolAddress((void**)&xn, g_xn);
    cudaGetSymbolAddress((void**)&q,  g_q);
    cudaGetSymbolAddress((void**)&k,  g_k);
    cudaGetSymbolAddress((void**)&v,  g_v);
    cudaGetSymbolAddress((void**)&o,  g_o);

    cudaFuncSetAttribute(flash_kernel,
                         cudaFuncAttributeMaxDynamicSharedMemorySize,
                         FLASH_SMEM_BYTES);

    ln_kernel<<<M_TOT, 256>>>(inputs, gamma, beta, xn);

    dim3 gg(CC / 64, M_TOT / 64);
    gemm_kernel<<<gg, 256>>>(xn,      Wq, bq, nullptr, q);
    gemm_kernel<<<gg, 256>>>(context, Wk, bk, nullptr, k);
    gemm_kernel<<<gg, 256>>>(context, Wv, bv, nullptr, v);

    flash_kernel<<<dim3(SS / 64, BN), 256, FLASH_SMEM_BYTES>>>(q, k, v, o);

    gemm_kernel<<<gg, 256>>>(o, Wp, bp, xn, out);
}